// round 3
// baseline (speedup 1.0000x reference)
#include <cuda_runtime.h>
#include <math_constants.h>

// Problem constants
#define N_ROWS 262144
#define DIMK   512
#define DIMV   512

#define BLOCKS          456              // 3 * 152 SMs — one wave at occ=3
#define TPB             256
#define WARPS_PER_BLOCK (TPB / 32)
#define TOTAL_WARPS     (BLOCKS * WARPS_PER_BLOCK)   // 3648
#define N_QUADS         (N_ROWS / 4)                 // 65536

// Scratch: per-BLOCK online-softmax partials + completion ticket
__device__ float g_bmax[BLOCKS];
__device__ float g_bsum[BLOCKS];
__device__ int   g_barg[BLOCKS];
__device__ int   g_ticket = 0;           // reset by last block each launch -> graph-replay safe

__device__ __forceinline__ float dot_row(const float4* __restrict__ k4,
                                         const float4& q0, const float4& q1,
                                         const float4& q2, const float4& q3,
                                         int lane) {
    // evict-streaming: keys have zero reuse
    float4 a = __ldcs(&k4[lane]);
    float4 b = __ldcs(&k4[lane + 32]);
    float4 c = __ldcs(&k4[lane + 64]);
    float4 d = __ldcs(&k4[lane + 96]);
    float acc;
    acc  = a.x * q0.x; acc = fmaf(a.y, q0.y, acc); acc = fmaf(a.z, q0.z, acc); acc = fmaf(a.w, q0.w, acc);
    acc  = fmaf(b.x, q1.x, acc); acc = fmaf(b.y, q1.y, acc); acc = fmaf(b.z, q1.z, acc); acc = fmaf(b.w, q1.w, acc);
    acc  = fmaf(c.x, q2.x, acc); acc = fmaf(c.y, q2.y, acc); acc = fmaf(c.z, q2.z, acc); acc = fmaf(c.w, q2.w, acc);
    acc  = fmaf(d.x, q3.x, acc); acc = fmaf(d.y, q3.y, acc); acc = fmaf(d.z, q3.z, acc); acc = fmaf(d.w, q3.w, acc);
    return acc;
}

// Merge (m2, s2, a2) into (m, s, arg) -- online softmax combine
__device__ __forceinline__ void osm_merge(float& m, float& s, int& arg,
                                          float m2, float s2, int a2) {
    float nm = fmaxf(m, m2);
    s = s * __expf(m - nm) + s2 * __expf(m2 - nm);
    if (m2 > m) arg = a2;
    m = nm;
}

__device__ __forceinline__ void osm_push(float& m, float& s, int& arg,
                                         float logit, int row) {
    float nm = fmaxf(m, logit);
    s = s * __expf(m - nm) + __expf(logit - nm);
    if (logit > m) arg = row;
    m = nm;
}

__global__ __launch_bounds__(TPB, 3)
void fused_kernel(const float* __restrict__ keys,
                  const float* __restrict__ query,
                  const float* __restrict__ values,
                  float* __restrict__ out) {
    const int tid   = threadIdx.x;
    const int lane  = tid & 31;
    const int wid   = tid >> 5;
    const int gwarp = blockIdx.x * WARPS_PER_BLOCK + wid;

    // Query in registers: each lane owns 16 floats (4 x float4)
    const float4* q4 = (const float4*)query;
    const float4 q0 = q4[lane];
    const float4 q1 = q4[lane + 32];
    const float4 q2 = q4[lane + 64];
    const float4 q3 = q4[lane + 96];

    float m = -CUDART_INF_F;
    float s = 0.0f;
    int   arg = 0;

    // Grid-strided row quads (4 rows / iteration, 16 LDG.128 in flight)
    #pragma unroll 1
    for (int q = gwarp; q < N_QUADS; q += TOTAL_WARPS) {
        const int row0 = 4 * q;
        const float4* k0 = (const float4*)(keys + (size_t)(row0 + 0) * DIMK);
        const float4* k1 = (const float4*)(keys + (size_t)(row0 + 1) * DIMK);
        const float4* k2 = (const float4*)(keys + (size_t)(row0 + 2) * DIMK);
        const float4* k3 = (const float4*)(keys + (size_t)(row0 + 3) * DIMK);

        float a0 = dot_row(k0, q0, q1, q2, q3, lane);
        float a1 = dot_row(k1, q0, q1, q2, q3, lane);
        float a2 = dot_row(k2, q0, q1, q2, q3, lane);
        float a3 = dot_row(k3, q0, q1, q2, q3, lane);

        // Four interleaved shuffle-reduction chains
        #pragma unroll
        for (int off = 16; off > 0; off >>= 1) {
            a0 += __shfl_xor_sync(0xffffffffu, a0, off);
            a1 += __shfl_xor_sync(0xffffffffu, a1, off);
            a2 += __shfl_xor_sync(0xffffffffu, a2, off);
            a3 += __shfl_xor_sync(0xffffffffu, a3, off);
        }

        osm_push(m, s, arg, a0, row0 + 0);
        osm_push(m, s, arg, a1, row0 + 1);
        osm_push(m, s, arg, a2, row0 + 2);
        osm_push(m, s, arg, a3, row0 + 3);
    }

    // ---- Block-level merge of 8 warp partials ----
    __shared__ float sm_m[WARPS_PER_BLOCK];
    __shared__ float sm_s[WARPS_PER_BLOCK];
    __shared__ int   sm_a[WARPS_PER_BLOCK];
    __shared__ bool  is_last;
    __shared__ int   s_best;
    __shared__ float s_inv;

    if (lane == 0) {
        sm_m[wid] = m; sm_s[wid] = s; sm_a[wid] = arg;
    }
    __syncthreads();

    if (tid == 0) {
        float bm = sm_m[0], bs = sm_s[0];
        int   ba = sm_a[0];
        #pragma unroll
        for (int w = 1; w < WARPS_PER_BLOCK; w++)
            osm_merge(bm, bs, ba, sm_m[w], sm_s[w], sm_a[w]);
        g_bmax[blockIdx.x] = bm;
        g_bsum[blockIdx.x] = bs;
        g_barg[blockIdx.x] = ba;
        __threadfence();
        int old = atomicAdd(&g_ticket, 1);
        is_last = (old == BLOCKS - 1);
    }
    __syncthreads();

    if (!is_last) return;

    // ---- Last block: warp 0 merges 456 block partials (lean, ~1us) ----
    if (wid == 0) {
        float lm = -CUDART_INF_F, ls = 0.0f;
        int   la = 0;
        #pragma unroll 1
        for (int i = lane; i < BLOCKS; i += 32)
            osm_merge(lm, ls, la, g_bmax[i], g_bsum[i], g_barg[i]);

        // Shuffle-based deterministic combine (butterfly)
        #pragma unroll
        for (int off = 16; off > 0; off >>= 1) {
            float m2 = __shfl_xor_sync(0xffffffffu, lm, off);
            float s2 = __shfl_xor_sync(0xffffffffu, ls, off);
            int   a2 = __shfl_xor_sync(0xffffffffu, la, off);
            // symmetric merge keeps all lanes identical
            float nm = fmaxf(lm, m2);
            ls = ls * __expf(lm - nm) + s2 * __expf(m2 - nm);
            if (m2 > lm) la = a2;
            lm = nm;
        }

        if (lane == 0) {
            s_best = la;
            s_inv  = 1.0f / ls;
            g_ticket = 0;   // reset for next graph replay
        }
    }
    __syncthreads();

    const int   best = s_best;
    const float inv  = s_inv;
    const float* vrow = values + (size_t)best * DIMV;

    out[tid]       = vrow[tid]       * inv;
    out[tid + TPB] = vrow[tid + TPB] * inv;
}

extern "C" void kernel_launch(void* const* d_in, const int* in_sizes, int n_in,
                              void* d_out, int out_size) {
    const float* query  = (const float*)d_in[0];
    const float* keys   = (const float*)d_in[1];
    const float* values = (const float*)d_in[2];
    float* out = (float*)d_out;

    fused_kernel<<<BLOCKS, TPB>>>(keys, query, values, out);
}